// round 1
// baseline (speedup 1.0000x reference)
#include <cuda_runtime.h>
#include <cuda_bf16.h>
#include <math.h>
#include <stdint.h>

// Problem constants
#define BB 2
#define SS 2048
#define DD 1024
#define HH 16
#define HD 64
#define RA 32
#define RF 512
#define RO 512
#define INTER 4096
#define BS (BB * SS)          // 4096 rows
#define CLAMP_V 1.0e6f
#define LN_EPS 1e-5f

// ---------------------------------------------------------------------------
// Scratch (device globals: allocation-free)
// ---------------------------------------------------------------------------
__device__ float g_normed[BS * DD];
__device__ float g_Tq[BS * (HH * RA)];
__device__ float g_Tk[BS * (HH * RA)];
__device__ float g_Tv[BS * (HH * RA)];
__device__ float g_q[BB * HH * SS * HD];
__device__ float g_k[BB * HH * SS * HD];
__device__ float g_v[BB * HH * SS * HD];
__device__ float g_attn[BS * DD];
__device__ float g_h[BS * DD];
__device__ float g_tmp[BS * 512];
__device__ float g_ff[BS * INTER];

// ---------------------------------------------------------------------------
// LayerNorm: one block per row (D = 1024, 256 threads, 4 elems/thread)
// ---------------------------------------------------------------------------
__global__ __launch_bounds__(256) void ln_kernel(
    const float* __restrict__ x, const float* __restrict__ w,
    const float* __restrict__ b, float* __restrict__ y)
{
    __shared__ float warpred[8];
    __shared__ float s_mean, s_var;
    const int row = blockIdx.x;
    const int tid = threadIdx.x;
    const float* xr = x + (size_t)row * DD;

    float v[4];
    float local = 0.f;
#pragma unroll
    for (int i = 0; i < 4; i++) {
        v[i] = xr[tid + 256 * i];
        local += v[i];
    }
#pragma unroll
    for (int off = 16; off > 0; off >>= 1)
        local += __shfl_xor_sync(0xffffffffu, local, off);
    if ((tid & 31) == 0) warpred[tid >> 5] = local;
    __syncthreads();
    if (tid == 0) {
        float s = 0.f;
#pragma unroll
        for (int i = 0; i < 8; i++) s += warpred[i];
        s_mean = s * (1.0f / DD);
    }
    __syncthreads();
    const float mean = s_mean;

    local = 0.f;
#pragma unroll
    for (int i = 0; i < 4; i++) {
        float d = v[i] - mean;
        local += d * d;
    }
#pragma unroll
    for (int off = 16; off > 0; off >>= 1)
        local += __shfl_xor_sync(0xffffffffu, local, off);
    if ((tid & 31) == 0) warpred[tid >> 5] = local;
    __syncthreads();
    if (tid == 0) {
        float s = 0.f;
#pragma unroll
        for (int i = 0; i < 8; i++) s += warpred[i];
        s_var = s * (1.0f / DD);
    }
    __syncthreads();
    const float rstd = rsqrtf(s_var + LN_EPS);

    float* yr = y + (size_t)row * DD;
#pragma unroll
    for (int i = 0; i < 4; i++) {
        int d = tid + 256 * i;
        yr[d] = (v[i] - mean) * rstd * w[d] + b[d];
    }
}

// ---------------------------------------------------------------------------
// Generic NT SGEMM: C[M,N] = A[M,K] * W[N,K]^T (+bias / gelu / residual)
// BM=BN=128, BK=8, TM=TN=8, 256 threads. Requires M%128==0, N%128==0, K%8==0.
// EPI: 0 = (+bias) ; 1 = (+bias) then exact GELU ; 2 = (+bias) + residual
// ---------------------------------------------------------------------------
#define GBM 128
#define GBN 128
#define GBK 8
#define GTM 8
#define GTN 8

template <int EPI>
__global__ __launch_bounds__(256) void sgemm_nt(
    int M, int N, int K,
    const float* __restrict__ A, const float* __restrict__ W,
    const float* __restrict__ bias, const float* __restrict__ res,
    float* __restrict__ C)
{
    __shared__ float As[GBK][GBM];
    __shared__ float Ws[GBK][GBN];

    const int bm = blockIdx.y * GBM;
    const int bn = blockIdx.x * GBN;
    const int tid = threadIdx.x;

    const int ldRow  = tid >> 1;         // 0..127
    const int ldCol4 = (tid & 1) * 4;    // 0 or 4

    const int tr = (tid >> 4) * GTM;     // 0..120
    const int tc = (tid & 15) * GTN;     // 0..120

    const float* Ab = A + (size_t)bm * K;
    const float* Wb = W + (size_t)bn * K;

    float acc[GTM][GTN];
#pragma unroll
    for (int i = 0; i < GTM; i++)
#pragma unroll
        for (int j = 0; j < GTN; j++) acc[i][j] = 0.f;

    for (int k0 = 0; k0 < K; k0 += GBK) {
        float4 av = *reinterpret_cast<const float4*>(Ab + (size_t)ldRow * K + k0 + ldCol4);
        As[ldCol4 + 0][ldRow] = av.x;
        As[ldCol4 + 1][ldRow] = av.y;
        As[ldCol4 + 2][ldRow] = av.z;
        As[ldCol4 + 3][ldRow] = av.w;
        float4 wv = *reinterpret_cast<const float4*>(Wb + (size_t)ldRow * K + k0 + ldCol4);
        Ws[ldCol4 + 0][ldRow] = wv.x;
        Ws[ldCol4 + 1][ldRow] = wv.y;
        Ws[ldCol4 + 2][ldRow] = wv.z;
        Ws[ldCol4 + 3][ldRow] = wv.w;
        __syncthreads();

#pragma unroll
        for (int k = 0; k < GBK; k++) {
            float4 a0 = *reinterpret_cast<const float4*>(&As[k][tr]);
            float4 a1 = *reinterpret_cast<const float4*>(&As[k][tr + 4]);
            float4 b0 = *reinterpret_cast<const float4*>(&Ws[k][tc]);
            float4 b1 = *reinterpret_cast<const float4*>(&Ws[k][tc + 4]);
            float regA[GTM] = {a0.x, a0.y, a0.z, a0.w, a1.x, a1.y, a1.z, a1.w};
            float regB[GTN] = {b0.x, b0.y, b0.z, b0.w, b1.x, b1.y, b1.z, b1.w};
#pragma unroll
            for (int i = 0; i < GTM; i++)
#pragma unroll
                for (int j = 0; j < GTN; j++)
                    acc[i][j] += regA[i] * regB[j];
        }
        __syncthreads();
    }

#pragma unroll
    for (int i = 0; i < GTM; i++) {
        const int m = bm + tr + i;
#pragma unroll
        for (int j4 = 0; j4 < GTN; j4 += 4) {
            const int n = bn + tc + j4;
            float4 v;
            v.x = acc[i][j4 + 0];
            v.y = acc[i][j4 + 1];
            v.z = acc[i][j4 + 2];
            v.w = acc[i][j4 + 3];
            if (bias) {
                v.x += bias[n + 0];
                v.y += bias[n + 1];
                v.z += bias[n + 2];
                v.w += bias[n + 3];
            }
            if (EPI == 1) {
                v.x = 0.5f * v.x * (1.0f + erff(v.x * 0.70710678118654752f));
                v.y = 0.5f * v.y * (1.0f + erff(v.y * 0.70710678118654752f));
                v.z = 0.5f * v.z * (1.0f + erff(v.z * 0.70710678118654752f));
                v.w = 0.5f * v.w * (1.0f + erff(v.w * 0.70710678118654752f));
            }
            if (EPI == 2) {
                float4 r = *reinterpret_cast<const float4*>(res + (size_t)m * N + n);
                v.x += r.x; v.y += r.y; v.z += r.z; v.w += r.w;
            }
            *reinterpret_cast<float4*>(C + (size_t)m * N + n) = v;
        }
    }
}

// ---------------------------------------------------------------------------
// Per-head U projection: out[b,h,s,e] = clip(sum_r T[bs, h*32+r] * U[h,e,r] + bias[h,e])
// grid: (BS/64, H), 256 threads. T ld = 512.
// ---------------------------------------------------------------------------
__global__ __launch_bounds__(256) void uproj_kernel(
    const float* __restrict__ T, const float* __restrict__ U,
    const float* __restrict__ bias, float* __restrict__ out)
{
    __shared__ float Us[HD][RA + 1];
    __shared__ float Ts[64][RA + 1];
    const int h  = blockIdx.y;
    const int s0 = blockIdx.x * 64;     // global bs row base
    const int tid = threadIdx.x;

    // load U[h]: 64x32 = 2048 elems
#pragma unroll
    for (int i = 0; i < 8; i++) {
        int idx = tid + 256 * i;
        Us[idx >> 5][idx & 31] = U[(size_t)h * (HD * RA) + idx];
    }
    // load T tile: 64 rows x 32 r
#pragma unroll
    for (int i = 0; i < 8; i++) {
        int idx = tid + 256 * i;
        int sl = idx >> 5, r = idx & 31;
        Ts[sl][r] = T[(size_t)(s0 + sl) * (HH * RA) + h * RA + r];
    }
    __syncthreads();

    const int sl = tid >> 2;       // 0..63
    const int eg = tid & 3;        // 0..3, e = eg + 4*i
    float accv[16];
#pragma unroll
    for (int i = 0; i < 16; i++) accv[i] = 0.f;
#pragma unroll
    for (int r = 0; r < RA; r++) {
        float t = Ts[sl][r];
#pragma unroll
        for (int i = 0; i < 16; i++)
            accv[i] += t * Us[eg + 4 * i][r];
    }

    const int bs = s0 + sl;
    const int b = bs / SS;
    const int s = bs - b * SS;
    float* op = out + (((size_t)(b * HH + h) * SS) + s) * HD;
#pragma unroll
    for (int i = 0; i < 16; i++) {
        int e = eg + 4 * i;
        float v = accv[i] + bias[h * HD + e];
        v = fminf(fmaxf(v, -CLAMP_V), CLAMP_V);
        op[e] = v;
    }
}

// ---------------------------------------------------------------------------
// Causal flash attention, fp32. Q,K,V: [B,H,S,64]; O: [B,S,H,64].
// 64x64 tiles, 256 threads; thread tile = 2 rows x 8 cols.
// Dynamic smem: Qs,Ks,Vs,Ps each 64x65 floats = 66560 B.
// ---------------------------------------------------------------------------
#define ATT_PAD 65
#define ATT_SMEM (4 * 64 * ATT_PAD * (int)sizeof(float))

__global__ __launch_bounds__(256) void attn_kernel(
    const float* __restrict__ Q, const float* __restrict__ K,
    const float* __restrict__ V, float* __restrict__ O)
{
    extern __shared__ float sm[];
    float* Qs = sm;
    float* Ks = Qs + 64 * ATT_PAD;
    float* Vs = Ks + 64 * ATT_PAD;
    float* Ps = Vs + 64 * ATT_PAD;

    const int bh = blockIdx.y;           // b*H + h
    const int b = bh / HH;
    const int h = bh - b * HH;
    const int qt = blockIdx.x;
    const int tid = threadIdx.x;
    const int rg = tid >> 3;             // 0..31
    const int cg = tid & 7;              // 0..7
    const int r0 = rg, r1 = rg + 32;

    const float* Qb = Q + ((size_t)bh * SS + qt * 64) * HD;
#pragma unroll
    for (int i = 0; i < 16; i++) {
        int idx = tid + 256 * i;
        Qs[(idx >> 6) * ATT_PAD + (idx & 63)] = Qb[idx];
    }

    float m0 = -1e30f, m1 = -1e30f, l0 = 0.f, l1 = 0.f;
    float o0[8], o1[8];
#pragma unroll
    for (int j = 0; j < 8; j++) { o0[j] = 0.f; o1[j] = 0.f; }

    const int qg0 = qt * 64 + r0;
    const int qg1 = qt * 64 + r1;

    for (int jt = 0; jt <= qt; jt++) {
        __syncthreads();   // previous PV done before overwriting K/V tiles
        const float* Kb = K + ((size_t)bh * SS + jt * 64) * HD;
        const float* Vb = V + ((size_t)bh * SS + jt * 64) * HD;
#pragma unroll
        for (int i = 0; i < 16; i++) {
            int idx = tid + 256 * i;
            int rr = idx >> 6, dd = idx & 63;
            Ks[rr * ATT_PAD + dd] = Kb[idx];
            Vs[rr * ATT_PAD + dd] = Vb[idx];
        }
        __syncthreads();

        // scores: 2 rows x 8 cols per thread
        float s0[8], s1[8];
#pragma unroll
        for (int j = 0; j < 8; j++) { s0[j] = 0.f; s1[j] = 0.f; }
        const int cbase = cg * 8;
#pragma unroll 4
        for (int d = 0; d < HD; d++) {
            float q0 = Qs[r0 * ATT_PAD + d];
            float q1 = Qs[r1 * ATT_PAD + d];
#pragma unroll
            for (int j = 0; j < 8; j++) {
                float kv = Ks[(cbase + j) * ATT_PAD + d];
                s0[j] += q0 * kv;
                s1[j] += q1 * kv;
            }
        }
        const int colg = jt * 64 + cbase;
#pragma unroll
        for (int j = 0; j < 8; j++) {
            s0[j] *= 0.125f;
            s1[j] *= 0.125f;
            if (colg + j > qg0) s0[j] = -1e30f;
            if (colg + j > qg1) s1[j] = -1e30f;
        }

        // row max over 64 cols (8 local + xor-shfl over 8 threads)
        float mt0 = s0[0], mt1 = s1[0];
#pragma unroll
        for (int j = 1; j < 8; j++) { mt0 = fmaxf(mt0, s0[j]); mt1 = fmaxf(mt1, s1[j]); }
#pragma unroll
        for (int off = 1; off < 8; off <<= 1) {
            mt0 = fmaxf(mt0, __shfl_xor_sync(0xffffffffu, mt0, off));
            mt1 = fmaxf(mt1, __shfl_xor_sync(0xffffffffu, mt1, off));
        }
        const float mn0 = fmaxf(m0, mt0);
        const float mn1 = fmaxf(m1, mt1);
        const float al0 = __expf(m0 - mn0);
        const float al1 = __expf(m1 - mn1);

        float sp0 = 0.f, sp1 = 0.f;
        float p0[8], p1[8];
#pragma unroll
        for (int j = 0; j < 8; j++) {
            p0[j] = __expf(s0[j] - mn0);
            p1[j] = __expf(s1[j] - mn1);
            sp0 += p0[j];
            sp1 += p1[j];
        }
#pragma unroll
        for (int off = 1; off < 8; off <<= 1) {
            sp0 += __shfl_xor_sync(0xffffffffu, sp0, off);
            sp1 += __shfl_xor_sync(0xffffffffu, sp1, off);
        }
        l0 = l0 * al0 + sp0;
        l1 = l1 * al1 + sp1;
        m0 = mn0; m1 = mn1;
#pragma unroll
        for (int j = 0; j < 8; j++) { o0[j] *= al0; o1[j] *= al1; }

#pragma unroll
        for (int j = 0; j < 8; j++) {
            Ps[r0 * ATT_PAD + cbase + j] = p0[j];
            Ps[r1 * ATT_PAD + cbase + j] = p1[j];
        }
        __syncthreads();

        // PV: o[row][e] += sum_c P[row][c] * V[c][e], e = cg*8..+7
#pragma unroll 4
        for (int c = 0; c < 64; c++) {
            float pa = Ps[r0 * ATT_PAD + c];
            float pb = Ps[r1 * ATT_PAD + c];
#pragma unroll
            for (int j = 0; j < 8; j++) {
                float vv = Vs[c * ATT_PAD + cbase + j];
                o0[j] += pa * vv;
                o1[j] += pb * vv;
            }
        }
    }

    const float inv0 = 1.0f / l0;
    const float inv1 = 1.0f / l1;
    // O layout [B,S,H,HD]
    float* op0 = O + (((size_t)b * SS + qg0) * HH + h) * HD + cg * 8;
    float* op1 = O + (((size_t)b * SS + qg1) * HH + h) * HD + cg * 8;
#pragma unroll
    for (int j = 0; j < 8; j++) {
        op0[j] = o0[j] * inv0;
        op1[j] = o1[j] * inv1;
    }
}

// ---------------------------------------------------------------------------
// Host launch
// ---------------------------------------------------------------------------
extern "C" void kernel_launch(void* const* d_in, const int* in_sizes, int n_in,
                              void* d_out, int out_size)
{
    const float* hidden   = (const float*)d_in[0];
    const float* q_U      = (const float*)d_in[1];
    const float* q_V      = (const float*)d_in[2];
    const float* q_bias   = (const float*)d_in[3];
    const float* k_U      = (const float*)d_in[4];
    const float* k_V      = (const float*)d_in[5];
    const float* k_bias   = (const float*)d_in[6];
    const float* v_U      = (const float*)d_in[7];
    const float* v_V      = (const float*)d_in[8];
    const float* v_bias   = (const float*)d_in[9];
    const float* out_U    = (const float*)d_in[10];
    const float* out_V    = (const float*)d_in[11];
    const float* out_bias = (const float*)d_in[12];
    const float* fc1_U    = (const float*)d_in[13];
    const float* fc1_V    = (const float*)d_in[14];
    const float* fc1_bias = (const float*)d_in[15];
    const float* fc2_U    = (const float*)d_in[16];
    const float* fc2_V    = (const float*)d_in[17];
    const float* fc2_bias = (const float*)d_in[18];
    const float* ln1_w    = (const float*)d_in[19];
    const float* ln1_b    = (const float*)d_in[20];
    const float* ln2_w    = (const float*)d_in[21];
    const float* ln2_b    = (const float*)d_in[22];
    float* out = (float*)d_out;

    float *p_normed, *p_Tq, *p_Tk, *p_Tv, *p_q, *p_k, *p_v, *p_attn, *p_h, *p_tmp, *p_ff;
    cudaGetSymbolAddress((void**)&p_normed, g_normed);
    cudaGetSymbolAddress((void**)&p_Tq, g_Tq);
    cudaGetSymbolAddress((void**)&p_Tk, g_Tk);
    cudaGetSymbolAddress((void**)&p_Tv, g_Tv);
    cudaGetSymbolAddress((void**)&p_q, g_q);
    cudaGetSymbolAddress((void**)&p_k, g_k);
    cudaGetSymbolAddress((void**)&p_v, g_v);
    cudaGetSymbolAddress((void**)&p_attn, g_attn);
    cudaGetSymbolAddress((void**)&p_h, g_h);
    cudaGetSymbolAddress((void**)&p_tmp, g_tmp);
    cudaGetSymbolAddress((void**)&p_ff, g_ff);

    cudaFuncSetAttribute(attn_kernel, cudaFuncAttributeMaxDynamicSharedMemorySize, ATT_SMEM);

    // 1. LN1
    ln_kernel<<<BS, 256>>>(hidden, ln1_w, ln1_b, p_normed);

    // 2. rank projections: T = normed @ V^T  (N = H*RA = 512, K = 1024)
    {
        dim3 g(512 / GBN, BS / GBM);
        sgemm_nt<0><<<g, 256>>>(BS, 512, DD, p_normed, q_V, nullptr, nullptr, p_Tq);
        sgemm_nt<0><<<g, 256>>>(BS, 512, DD, p_normed, k_V, nullptr, nullptr, p_Tk);
        sgemm_nt<0><<<g, 256>>>(BS, 512, DD, p_normed, v_V, nullptr, nullptr, p_Tv);
    }

    // 3. U projection + bias + clip -> q,k,v [B,H,S,HD]
    {
        dim3 g(BS / 64, HH);
        uproj_kernel<<<g, 256>>>(p_Tq, q_U, q_bias, p_q);
        uproj_kernel<<<g, 256>>>(p_Tk, k_U, k_bias, p_k);
        uproj_kernel<<<g, 256>>>(p_Tv, v_U, v_bias, p_v);
    }

    // 4. causal attention -> attn [B,S,H*HD]
    {
        dim3 g(SS / 64, BB * HH);
        attn_kernel<<<g, 256, ATT_SMEM>>>(p_q, p_k, p_v, p_attn);
    }

    // 5-6. out projection (low rank) + residual
    {
        dim3 g1(RO / GBN, BS / GBM);
        sgemm_nt<0><<<g1, 256>>>(BS, RO, DD, p_attn, out_V, nullptr, nullptr, p_tmp);
        dim3 g2(DD / GBN, BS / GBM);
        sgemm_nt<2><<<g2, 256>>>(BS, DD, RO, p_tmp, out_U, out_bias, hidden, p_h);
    }

    // 7. LN2
    ln_kernel<<<BS, 256>>>(p_h, ln2_w, ln2_b, p_normed);

    // 8-9. FC1 (low rank) + bias + exact GELU
    {
        dim3 g1(RF / GBN, BS / GBM);
        sgemm_nt<0><<<g1, 256>>>(BS, RF, DD, p_normed, fc1_V, nullptr, nullptr, p_tmp);
        dim3 g2(INTER / GBN, BS / GBM);
        sgemm_nt<1><<<g2, 256>>>(BS, INTER, RF, p_tmp, fc1_U, fc1_bias, nullptr, p_ff);
    }

    // 10-11. FC2 (low rank) + bias + residual -> out
    {
        dim3 g1(RF / GBN, BS / GBM);
        sgemm_nt<0><<<g1, 256>>>(BS, RF, INTER, p_ff, fc2_V, nullptr, nullptr, p_tmp);
        dim3 g2(DD / GBN, BS / GBM);
        sgemm_nt<2><<<g2, 256>>>(BS, DD, RF, p_tmp, fc2_U, fc2_bias, p_h, out);
    }
    (void)in_sizes; (void)n_in; (void)out_size;
}

// round 3
// speedup vs baseline: 1.6499x; 1.6499x over previous
#include <cuda_runtime.h>
#include <cuda_bf16.h>
#include <math.h>
#include <stdint.h>

// Problem constants
#define BB 2
#define SS 2048
#define DD 1024
#define HH 16
#define HD 64
#define RA 32
#define RF 512
#define RO 512
#define INTER 4096
#define BS (BB * SS)          // 4096 rows
#define CLAMP_V 1.0e6f
#define LN_EPS 1e-5f

// ---------------------------------------------------------------------------
// Scratch (device globals: allocation-free)
// ---------------------------------------------------------------------------
__device__ float g_normed[BS * DD];
__device__ float g_Tq[BS * (HH * RA)];
__device__ float g_Tk[BS * (HH * RA)];
__device__ float g_Tv[BS * (HH * RA)];
__device__ float g_q[BB * HH * SS * HD];
__device__ float g_k[BB * HH * SS * HD];
__device__ float g_v[BB * HH * SS * HD];
__device__ float g_attn[BS * DD];
__device__ float g_h[BS * DD];
__device__ float g_tmp[BS * 512];
__device__ float g_ff[BS * INTER];

// ---------------------------------------------------------------------------
// mma.sync bf16 GEMM with 3-term split: C = A[M,K] * W[N,K]^T (+epilogues)
// Block 128x128, BK=32, 8 warps (2x4), warp tile 64x32.
// smem: per stage {Ah, Al, Bh, Bl}, 128 rows x 40 bf16 (80B stride), 2 stages.
// EPI: 0 = (+bias); 1 = (+bias)+exact GELU; 2 = (+bias)+residual
// ---------------------------------------------------------------------------
#define MG_STRIDE 80                 // bytes per smem row (40 bf16)
#define MG_TILE   (128 * MG_STRIDE) // 10240 B
#define MG_STAGE  (4 * MG_TILE)     // 40960 B
#define MG_SMEM   (2 * MG_STAGE)    // 81920 B

__device__ __forceinline__ void mma16816(float* c, const uint32_t* a, const uint32_t* b) {
    asm volatile(
        "mma.sync.aligned.m16n8k16.row.col.f32.bf16.bf16.f32 "
        "{%0,%1,%2,%3}, {%4,%5,%6,%7}, {%8,%9}, {%0,%1,%2,%3};"
        : "+f"(c[0]), "+f"(c[1]), "+f"(c[2]), "+f"(c[3])
        : "r"(a[0]), "r"(a[1]), "r"(a[2]), "r"(a[3]), "r"(b[0]), "r"(b[1]));
}

// convert 8 consecutive floats (two float4) -> hi uint4 + lo uint4 (bf16x2 each)
__device__ __forceinline__ void split8(const float4& f0, const float4& f1,
                                       uint4& hi, uint4& lo) {
    float f[8] = {f0.x, f0.y, f0.z, f0.w, f1.x, f1.y, f1.z, f1.w};
    uint32_t h[4], l[4];
#pragma unroll
    for (int j = 0; j < 4; j++) {
        uint32_t u0 = __float_as_uint(f[2 * j]);
        uint32_t u1 = __float_as_uint(f[2 * j + 1]);
        h[j] = __byte_perm(u0, u1, 0x7632);
        float h0 = __uint_as_float(u0 & 0xffff0000u);
        float h1 = __uint_as_float(u1 & 0xffff0000u);
        __nv_bfloat162 lv = __floats2bfloat162_rn(f[2 * j] - h0, f[2 * j + 1] - h1);
        l[j] = *reinterpret_cast<uint32_t*>(&lv);
    }
    hi = make_uint4(h[0], h[1], h[2], h[3]);
    lo = make_uint4(l[0], l[1], l[2], l[3]);
}

template <int EPI>
__global__ __launch_bounds__(256) void mma_gemm(
    int M, int N, int K,
    const float* __restrict__ A, const float* __restrict__ W,
    const float* __restrict__ bias, const float* __restrict__ res,
    float* __restrict__ C)
{
    extern __shared__ char sm[];
    const int tid = threadIdx.x;
    const int lane = tid & 31;
    const int warp = tid >> 5;
    const int wm = (warp >> 2) * 64;    // warp M offset in tile
    const int wn = (warp & 3) * 32;     // warp N offset
    const int bm = blockIdx.y * 128;
    const int bn = blockIdx.x * 128;

    // loader indices: thread handles rows (tid>>2) and (tid>>2)+64, colgroup (tid&3)*8
    const int ldRow = tid >> 2;
    const int ldCol = (tid & 3) * 8;

    // fragment indices
    const int aRow = wm + (lane >> 2);
    const int bRow = wn + (lane >> 2);
    const int fCol = (lane & 3) * 4;    // byte offset of (lane&3)*2 bf16

    float acc[4][4][4];
#pragma unroll
    for (int i = 0; i < 4; i++)
#pragma unroll
        for (int j = 0; j < 4; j++)
#pragma unroll
            for (int k = 0; k < 4; k++) acc[i][j][k] = 0.f;

    const float* Ab = A + (size_t)bm * K;
    const float* Wb = W + (size_t)bn * K;
    const int nchunks = K >> 5;

    // ---- load chunk 0 into stage 0
    {
        float4 a0 = *reinterpret_cast<const float4*>(Ab + (size_t)ldRow * K + ldCol);
        float4 a1 = *reinterpret_cast<const float4*>(Ab + (size_t)ldRow * K + ldCol + 4);
        float4 a2 = *reinterpret_cast<const float4*>(Ab + (size_t)(ldRow + 64) * K + ldCol);
        float4 a3 = *reinterpret_cast<const float4*>(Ab + (size_t)(ldRow + 64) * K + ldCol + 4);
        float4 b0 = *reinterpret_cast<const float4*>(Wb + (size_t)ldRow * K + ldCol);
        float4 b1 = *reinterpret_cast<const float4*>(Wb + (size_t)ldRow * K + ldCol + 4);
        float4 b2 = *reinterpret_cast<const float4*>(Wb + (size_t)(ldRow + 64) * K + ldCol);
        float4 b3 = *reinterpret_cast<const float4*>(Wb + (size_t)(ldRow + 64) * K + ldCol + 4);
        uint4 hi, lo;
        const int cb = ldCol * 2;
        split8(a0, a1, hi, lo);
        *reinterpret_cast<uint4*>(sm + 0 * MG_TILE + ldRow * MG_STRIDE + cb) = hi;
        *reinterpret_cast<uint4*>(sm + 1 * MG_TILE + ldRow * MG_STRIDE + cb) = lo;
        split8(a2, a3, hi, lo);
        *reinterpret_cast<uint4*>(sm + 0 * MG_TILE + (ldRow + 64) * MG_STRIDE + cb) = hi;
        *reinterpret_cast<uint4*>(sm + 1 * MG_TILE + (ldRow + 64) * MG_STRIDE + cb) = lo;
        split8(b0, b1, hi, lo);
        *reinterpret_cast<uint4*>(sm + 2 * MG_TILE + ldRow * MG_STRIDE + cb) = hi;
        *reinterpret_cast<uint4*>(sm + 3 * MG_TILE + ldRow * MG_STRIDE + cb) = lo;
        split8(b2, b3, hi, lo);
        *reinterpret_cast<uint4*>(sm + 2 * MG_TILE + (ldRow + 64) * MG_STRIDE + cb) = hi;
        *reinterpret_cast<uint4*>(sm + 3 * MG_TILE + (ldRow + 64) * MG_STRIDE + cb) = lo;
    }
    __syncthreads();

    for (int c = 0; c < nchunks; c++) {
        const int b = c & 1;
        char* st = sm + b * MG_STAGE;

        // prefetch chunk c+1 into registers (overlaps with MMA below)
        float4 pa0, pa1, pa2, pa3, pb0, pb1, pb2, pb3;
        const bool havenext = (c + 1 < nchunks);
        if (havenext) {
            const int k0 = (c + 1) << 5;
            pa0 = *reinterpret_cast<const float4*>(Ab + (size_t)ldRow * K + k0 + ldCol);
            pa1 = *reinterpret_cast<const float4*>(Ab + (size_t)ldRow * K + k0 + ldCol + 4);
            pa2 = *reinterpret_cast<const float4*>(Ab + (size_t)(ldRow + 64) * K + k0 + ldCol);
            pa3 = *reinterpret_cast<const float4*>(Ab + (size_t)(ldRow + 64) * K + k0 + ldCol + 4);
            pb0 = *reinterpret_cast<const float4*>(Wb + (size_t)ldRow * K + k0 + ldCol);
            pb1 = *reinterpret_cast<const float4*>(Wb + (size_t)ldRow * K + k0 + ldCol + 4);
            pb2 = *reinterpret_cast<const float4*>(Wb + (size_t)(ldRow + 64) * K + k0 + ldCol);
            pb3 = *reinterpret_cast<const float4*>(Wb + (size_t)(ldRow + 64) * K + k0 + ldCol + 4);
        }

        // MMA over this chunk: 2 k-steps of 16
#pragma unroll
        for (int kk = 0; kk < 2; kk++) {
            const int kb = kk * 32;   // byte offset: 16 bf16
            uint32_t ah[4][4], bh[4][2];
#pragma unroll
            for (int mt = 0; mt < 4; mt++) {
                const char* p = st + 0 * MG_TILE + (aRow + mt * 16) * MG_STRIDE + fCol + kb;
                ah[mt][0] = *reinterpret_cast<const uint32_t*>(p);
                ah[mt][1] = *reinterpret_cast<const uint32_t*>(p + 8 * MG_STRIDE);
                ah[mt][2] = *reinterpret_cast<const uint32_t*>(p + 16);
                ah[mt][3] = *reinterpret_cast<const uint32_t*>(p + 8 * MG_STRIDE + 16);
            }
#pragma unroll
            for (int nt = 0; nt < 4; nt++) {
                const char* p = st + 2 * MG_TILE + (bRow + nt * 8) * MG_STRIDE + fCol + kb;
                bh[nt][0] = *reinterpret_cast<const uint32_t*>(p);
                bh[nt][1] = *reinterpret_cast<const uint32_t*>(p + 16);
            }
#pragma unroll
            for (int mt = 0; mt < 4; mt++)
#pragma unroll
                for (int nt = 0; nt < 4; nt++)
                    mma16816(acc[mt][nt], ah[mt], bh[nt]);

            // Al * Bh
            {
                uint32_t al[4][4];
#pragma unroll
                for (int mt = 0; mt < 4; mt++) {
                    const char* p = st + 1 * MG_TILE + (aRow + mt * 16) * MG_STRIDE + fCol + kb;
                    al[mt][0] = *reinterpret_cast<const uint32_t*>(p);
                    al[mt][1] = *reinterpret_cast<const uint32_t*>(p + 8 * MG_STRIDE);
                    al[mt][2] = *reinterpret_cast<const uint32_t*>(p + 16);
                    al[mt][3] = *reinterpret_cast<const uint32_t*>(p + 8 * MG_STRIDE + 16);
                }
#pragma unroll
                for (int mt = 0; mt < 4; mt++)
#pragma unroll
                    for (int nt = 0; nt < 4; nt++)
                        mma16816(acc[mt][nt], al[mt], bh[nt]);
            }
            // Ah * Bl
            {
                uint32_t bl[4][2];
#pragma unroll
                for (int nt = 0; nt < 4; nt++) {
                    const char* p = st + 3 * MG_TILE + (bRow + nt * 8) * MG_STRIDE + fCol + kb;
                    bl[nt][0] = *reinterpret_cast<const uint32_t*>(p);
                    bl[nt][1] = *reinterpret_cast<const uint32_t*>(p + 16);
                }
#pragma unroll
                for (int mt = 0; mt < 4; mt++)
#pragma unroll
                    for (int nt = 0; nt < 4; nt++)
                        mma16816(acc[mt][nt], ah[mt], bl[nt]);
            }
        }

        if (havenext) {
            char* nst = sm + (b ^ 1) * MG_STAGE;
            const int cb = ldCol * 2;
            uint4 hi, lo;
            split8(pa0, pa1, hi, lo);
            *reinterpret_cast<uint4*>(nst + 0 * MG_TILE + ldRow * MG_STRIDE + cb) = hi;
            *reinterpret_cast<uint4*>(nst + 1 * MG_TILE + ldRow * MG_STRIDE + cb) = lo;
            split8(pa2, pa3, hi, lo);
            *reinterpret_cast<uint4*>(nst + 0 * MG_TILE + (ldRow + 64) * MG_STRIDE + cb) = hi;
            *reinterpret_cast<uint4*>(nst + 1 * MG_TILE + (ldRow + 64) * MG_STRIDE + cb) = lo;
            split8(pb0, pb1, hi, lo);
            *reinterpret_cast<uint4*>(nst + 2 * MG_TILE + ldRow * MG_STRIDE + cb) = hi;
            *reinterpret_cast<uint4*>(nst + 3 * MG_TILE + ldRow * MG_STRIDE + cb) = lo;
            split8(pb2, pb3, hi, lo);
            *reinterpret_cast<uint4*>(nst + 2 * MG_TILE + (ldRow + 64) * MG_STRIDE + cb) = hi;
            *reinterpret_cast<uint4*>(nst + 3 * MG_TILE + (ldRow + 64) * MG_STRIDE + cb) = lo;
        }
        __syncthreads();
    }

    // ---- epilogue from register accumulators
#pragma unroll
    for (int mt = 0; mt < 4; mt++) {
#pragma unroll
        for (int nt = 0; nt < 4; nt++) {
            const float* cc = acc[mt][nt];
            const int gr = bm + wm + mt * 16 + (lane >> 2);
            const int gc = bn + wn + nt * 8 + (lane & 3) * 2;
            float b0 = 0.f, b1 = 0.f;
            if (bias) { b0 = bias[gc]; b1 = bias[gc + 1]; }
#pragma unroll
            for (int half = 0; half < 2; half++) {
                const int row = gr + half * 8;
                float v0 = cc[half * 2 + 0] + b0;
                float v1 = cc[half * 2 + 1] + b1;
                if (EPI == 1) {
                    v0 = 0.5f * v0 * (1.0f + erff(v0 * 0.70710678118654752f));
                    v1 = 0.5f * v1 * (1.0f + erff(v1 * 0.70710678118654752f));
                }
                if (EPI == 2) {
                    float2 r2 = *reinterpret_cast<const float2*>(res + (size_t)row * N + gc);
                    v0 += r2.x; v1 += r2.y;
                }
                *reinterpret_cast<float2*>(C + (size_t)row * N + gc) = make_float2(v0, v1);
            }
        }
    }
}

// ---------------------------------------------------------------------------
// LayerNorm: one block per row (D = 1024, 256 threads, 4 elems/thread)
// ---------------------------------------------------------------------------
__global__ __launch_bounds__(256) void ln_kernel(
    const float* __restrict__ x, const float* __restrict__ w,
    const float* __restrict__ b, float* __restrict__ y)
{
    __shared__ float warpred[8];
    __shared__ float s_mean, s_var;
    const int row = blockIdx.x;
    const int tid = threadIdx.x;
    const float* xr = x + (size_t)row * DD;

    float v[4];
    float local = 0.f;
#pragma unroll
    for (int i = 0; i < 4; i++) {
        v[i] = xr[tid + 256 * i];
        local += v[i];
    }
#pragma unroll
    for (int off = 16; off > 0; off >>= 1)
        local += __shfl_xor_sync(0xffffffffu, local, off);
    if ((tid & 31) == 0) warpred[tid >> 5] = local;
    __syncthreads();
    if (tid == 0) {
        float s = 0.f;
#pragma unroll
        for (int i = 0; i < 8; i++) s += warpred[i];
        s_mean = s * (1.0f / DD);
    }
    __syncthreads();
    const float mean = s_mean;

    local = 0.f;
#pragma unroll
    for (int i = 0; i < 4; i++) {
        float d = v[i] - mean;
        local += d * d;
    }
#pragma unroll
    for (int off = 16; off > 0; off >>= 1)
        local += __shfl_xor_sync(0xffffffffu, local, off);
    if ((tid & 31) == 0) warpred[tid >> 5] = local;
    __syncthreads();
    if (tid == 0) {
        float s = 0.f;
#pragma unroll
        for (int i = 0; i < 8; i++) s += warpred[i];
        s_var = s * (1.0f / DD);
    }
    __syncthreads();
    const float rstd = rsqrtf(s_var + LN_EPS);

    float* yr = y + (size_t)row * DD;
#pragma unroll
    for (int i = 0; i < 4; i++) {
        int d = tid + 256 * i;
        yr[d] = (v[i] - mean) * rstd * w[d] + b[d];
    }
}

// ---------------------------------------------------------------------------
// Per-head U projection: out[b,h,s,e] = clip(sum_r T[bs,h*32+r]*U[h,e,r]+bias)
// ---------------------------------------------------------------------------
__global__ __launch_bounds__(256) void uproj_kernel(
    const float* __restrict__ T, const float* __restrict__ U,
    const float* __restrict__ bias, float* __restrict__ out)
{
    __shared__ float Us[HD][RA + 1];
    __shared__ float Ts[64][RA + 1];
    const int h  = blockIdx.y;
    const int s0 = blockIdx.x * 64;
    const int tid = threadIdx.x;

#pragma unroll
    for (int i = 0; i < 8; i++) {
        int idx = tid + 256 * i;
        Us[idx >> 5][idx & 31] = U[(size_t)h * (HD * RA) + idx];
    }
#pragma unroll
    for (int i = 0; i < 8; i++) {
        int idx = tid + 256 * i;
        int sl = idx >> 5, r = idx & 31;
        Ts[sl][r] = T[(size_t)(s0 + sl) * (HH * RA) + h * RA + r];
    }
    __syncthreads();

    const int sl = tid >> 2;
    const int eg = tid & 3;
    float accv[16];
#pragma unroll
    for (int i = 0; i < 16; i++) accv[i] = 0.f;
#pragma unroll
    for (int r = 0; r < RA; r++) {
        float t = Ts[sl][r];
#pragma unroll
        for (int i = 0; i < 16; i++)
            accv[i] += t * Us[eg + 4 * i][r];
    }

    const int bs = s0 + sl;
    const int b = bs / SS;
    const int s = bs - b * SS;
    float* op = out + (((size_t)(b * HH + h) * SS) + s) * HD;
#pragma unroll
    for (int i = 0; i < 16; i++) {
        int e = eg + 4 * i;
        float v = accv[i] + bias[h * HD + e];
        v = fminf(fmaxf(v, -CLAMP_V), CLAMP_V);
        op[e] = v;
    }
}

// ---------------------------------------------------------------------------
// Causal flash attention, fp32. Q,K,V: [B,H,S,64]; O: [B,S,H,64].
// ---------------------------------------------------------------------------
#define ATT_PAD 65
#define ATT_SMEM (4 * 64 * ATT_PAD * (int)sizeof(float))

__global__ __launch_bounds__(256) void attn_kernel(
    const float* __restrict__ Q, const float* __restrict__ K,
    const float* __restrict__ V, float* __restrict__ O)
{
    extern __shared__ float smf[];
    float* Qs = smf;
    float* Ks = Qs + 64 * ATT_PAD;
    float* Vs = Ks + 64 * ATT_PAD;
    float* Ps = Vs + 64 * ATT_PAD;

    const int bh = blockIdx.y;
    const int b = bh / HH;
    const int h = bh - b * HH;
    const int qt = blockIdx.x;
    const int tid = threadIdx.x;
    const int rg = tid >> 3;
    const int cg = tid & 7;
    const int r0 = rg, r1 = rg + 32;

    const float* Qb = Q + ((size_t)bh * SS + qt * 64) * HD;
#pragma unroll
    for (int i = 0; i < 16; i++) {
        int idx = tid + 256 * i;
        Qs[(idx >> 6) * ATT_PAD + (idx & 63)] = Qb[idx];
    }

    float m0 = -1e30f, m1 = -1e30f, l0 = 0.f, l1 = 0.f;
    float o0[8], o1[8];
#pragma unroll
    for (int j = 0; j < 8; j++) { o0[j] = 0.f; o1[j] = 0.f; }

    const int qg0 = qt * 64 + r0;
    const int qg1 = qt * 64 + r1;

    for (int jt = 0; jt <= qt; jt++) {
        __syncthreads();
        const float* Kb = K + ((size_t)bh * SS + jt * 64) * HD;
        const float* Vb = V + ((size_t)bh * SS + jt * 64) * HD;
#pragma unroll
        for (int i = 0; i < 16; i++) {
            int idx = tid + 256 * i;
            int rr = idx >> 6, dd = idx & 63;
            Ks[rr * ATT_PAD + dd] = Kb[idx];
            Vs[rr * ATT_PAD + dd] = Vb[idx];
        }
        __syncthreads();

        float s0[8], s1[8];
#pragma unroll
        for (int j = 0; j < 8; j++) { s0[j] = 0.f; s1[j] = 0.f; }
        const int cbase = cg * 8;
#pragma unroll 4
        for (int d = 0; d < HD; d++) {
            float q0 = Qs[r0 * ATT_PAD + d];
            float q1 = Qs[r1 * ATT_PAD + d];
#pragma unroll
            for (int j = 0; j < 8; j++) {
                float kv = Ks[(cbase + j) * ATT_PAD + d];
                s0[j] += q0 * kv;
                s1[j] += q1 * kv;
            }
        }
        const int colg = jt * 64 + cbase;
#pragma unroll
        for (int j = 0; j < 8; j++) {
            s0[j] *= 0.125f;
            s1[j] *= 0.125f;
            if (colg + j > qg0) s0[j] = -1e30f;
            if (colg + j > qg1) s1[j] = -1e30f;
        }

        float mt0 = s0[0], mt1 = s1[0];
#pragma unroll
        for (int j = 1; j < 8; j++) { mt0 = fmaxf(mt0, s0[j]); mt1 = fmaxf(mt1, s1[j]); }
#pragma unroll
        for (int off = 1; off < 8; off <<= 1) {
            mt0 = fmaxf(mt0, __shfl_xor_sync(0xffffffffu, mt0, off));
            mt1 = fmaxf(mt1, __shfl_xor_sync(0xffffffffu, mt1, off));
        }
        const float mn0 = fmaxf(m0, mt0);
        const float mn1 = fmaxf(m1, mt1);
        const float al0 = __expf(m0 - mn0);
        const float al1 = __expf(m1 - mn1);

        float sp0 = 0.f, sp1 = 0.f;
        float p0[8], p1[8];
#pragma unroll
        for (int j = 0; j < 8; j++) {
            p0[j] = __expf(s0[j] - mn0);
            p1[j] = __expf(s1[j] - mn1);
            sp0 += p0[j];
            sp1 += p1[j];
        }
#pragma unroll
        for (int off = 1; off < 8; off <<= 1) {
            sp0 += __shfl_xor_sync(0xffffffffu, sp0, off);
            sp1 += __shfl_xor_sync(0xffffffffu, sp1, off);
        }
        l0 = l0 * al0 + sp0;
        l1 = l1 * al1 + sp1;
        m0 = mn0; m1 = mn1;
#pragma unroll
        for (int j = 0; j < 8; j++) { o0[j] *= al0; o1[j] *= al1; }

#pragma unroll
        for (int j = 0; j < 8; j++) {
            Ps[r0 * ATT_PAD + cbase + j] = p0[j];
            Ps[r1 * ATT_PAD + cbase + j] = p1[j];
        }
        __syncthreads();

#pragma unroll 4
        for (int c = 0; c < 64; c++) {
            float pa = Ps[r0 * ATT_PAD + c];
            float pb = Ps[r1 * ATT_PAD + c];
#pragma unroll
            for (int j = 0; j < 8; j++) {
                float vv = Vs[c * ATT_PAD + cbase + j];
                o0[j] += pa * vv;
                o1[j] += pb * vv;
            }
        }
    }

    const float inv0 = 1.0f / l0;
    const float inv1 = 1.0f / l1;
    float* op0 = O + (((size_t)b * SS + qg0) * HH + h) * HD + cg * 8;
    float* op1 = O + (((size_t)b * SS + qg1) * HH + h) * HD + cg * 8;
#pragma unroll
    for (int j = 0; j < 8; j++) {
        op0[j] = o0[j] * inv0;
        op1[j] = o1[j] * inv1;
    }
}

// ---------------------------------------------------------------------------
// Host launch
// ---------------------------------------------------------------------------
extern "C" void kernel_launch(void* const* d_in, const int* in_sizes, int n_in,
                              void* d_out, int out_size)
{
    const float* hidden   = (const float*)d_in[0];
    const float* q_U      = (const float*)d_in[1];
    const float* q_V      = (const float*)d_in[2];
    const float* q_bias   = (const float*)d_in[3];
    const float* k_U      = (const float*)d_in[4];
    const float* k_V      = (const float*)d_in[5];
    const float* k_bias   = (const float*)d_in[6];
    const float* v_U      = (const float*)d_in[7];
    const float* v_V      = (const float*)d_in[8];
    const float* v_bias   = (const float*)d_in[9];
    const float* out_U    = (const float*)d_in[10];
    const float* out_V    = (const float*)d_in[11];
    const float* out_bias = (const float*)d_in[12];
    const float* fc1_U    = (const float*)d_in[13];
    const float* fc1_V    = (const float*)d_in[14];
    const float* fc1_bias = (const float*)d_in[15];
    const float* fc2_U    = (const float*)d_in[16];
    const float* fc2_V    = (const float*)d_in[17];
    const float* fc2_bias = (const float*)d_in[18];
    const float* ln1_w    = (const float*)d_in[19];
    const float* ln1_b    = (const float*)d_in[20];
    const float* ln2_w    = (const float*)d_in[21];
    const float* ln2_b    = (const float*)d_in[22];
    float* out = (float*)d_out;

    float *p_normed, *p_Tq, *p_Tk, *p_Tv, *p_q, *p_k, *p_v, *p_attn, *p_h, *p_tmp, *p_ff;
    cudaGetSymbolAddress((void**)&p_normed, g_normed);
    cudaGetSymbolAddress((void**)&p_Tq, g_Tq);
    cudaGetSymbolAddress((void**)&p_Tk, g_Tk);
    cudaGetSymbolAddress((void**)&p_Tv, g_Tv);
    cudaGetSymbolAddress((void**)&p_q, g_q);
    cudaGetSymbolAddress((void**)&p_k, g_k);
    cudaGetSymbolAddress((void**)&p_v, g_v);
    cudaGetSymbolAddress((void**)&p_attn, g_attn);
    cudaGetSymbolAddress((void**)&p_h, g_h);
    cudaGetSymbolAddress((void**)&p_tmp, g_tmp);
    cudaGetSymbolAddress((void**)&p_ff, g_ff);

    cudaFuncSetAttribute(attn_kernel, cudaFuncAttributeMaxDynamicSharedMemorySize, ATT_SMEM);
    cudaFuncSetAttribute(mma_gemm<0>, cudaFuncAttributeMaxDynamicSharedMemorySize, MG_SMEM);
    cudaFuncSetAttribute(mma_gemm<1>, cudaFuncAttributeMaxDynamicSharedMemorySize, MG_SMEM);
    cudaFuncSetAttribute(mma_gemm<2>, cudaFuncAttributeMaxDynamicSharedMemorySize, MG_SMEM);

    // 1. LN1
    ln_kernel<<<BS, 256>>>(hidden, ln1_w, ln1_b, p_normed);

    // 2. rank projections: T = normed @ V^T  (N = 512, K = 1024)
    {
        dim3 g(512 / 128, BS / 128);
        mma_gemm<0><<<g, 256, MG_SMEM>>>(BS, 512, DD, p_normed, q_V, nullptr, nullptr, p_Tq);
        mma_gemm<0><<<g, 256, MG_SMEM>>>(BS, 512, DD, p_normed, k_V, nullptr, nullptr, p_Tk);
        mma_gemm<0><<<g, 256, MG_SMEM>>>(BS, 512, DD, p_normed, v_V, nullptr, nullptr, p_Tv);
    }

    // 3. U projection + bias + clip -> q,k,v [B,H,S,HD]
    {
        dim3 g(BS / 64, HH);
        uproj_kernel<<<g, 256>>>(p_Tq, q_U, q_bias, p_q);
        uproj_kernel<<<g, 256>>>(p_Tk, k_U, k_bias, p_k);
        uproj_kernel<<<g, 256>>>(p_Tv, v_U, v_bias, p_v);
    }

    // 4. causal attention -> attn [B,S,H*HD]
    {
        dim3 g(SS / 64, BB * HH);
        attn_kernel<<<g, 256, ATT_SMEM>>>(p_q, p_k, p_v, p_attn);
    }

    // 5-6. out projection (low rank) + residual
    {
        dim3 g1(RO / 128, BS / 128);
        mma_gemm<0><<<g1, 256, MG_SMEM>>>(BS, RO, DD, p_attn, out_V, nullptr, nullptr, p_tmp);
        dim3 g2(DD / 128, BS / 128);
        mma_gemm<2><<<g2, 256, MG_SMEM>>>(BS, DD, RO, p_tmp, out_U, out_bias, hidden, p_h);
    }

    // 7. LN2
    ln_kernel<<<BS, 256>>>(p_h, ln2_w, ln2_b, p_normed);

    // 8-9. FC1 (low rank) + bias + exact GELU
    {
        dim3 g1(RF / 128, BS / 128);
        mma_gemm<0><<<g1, 256, MG_SMEM>>>(BS, RF, DD, p_normed, fc1_V, nullptr, nullptr, p_tmp);
        dim3 g2(INTER / 128, BS / 128);
        mma_gemm<1><<<g2, 256, MG_SMEM>>>(BS, INTER, RF, p_tmp, fc1_U, fc1_bias, nullptr, p_ff);
    }

    // 10-11. FC2 (low rank) + bias + residual -> out
    {
        dim3 g1(RF / 128, BS / 128);
        mma_gemm<0><<<g1, 256, MG_SMEM>>>(BS, RF, INTER, p_ff, fc2_V, nullptr, nullptr, p_tmp);
        dim3 g2(DD / 128, BS / 128);
        mma_gemm<2><<<g2, 256, MG_SMEM>>>(BS, DD, RF, p_tmp, fc2_U, fc2_bias, p_h, out);
    }
    (void)in_sizes; (void)n_in; (void)out_size;
}

// round 4
// speedup vs baseline: 3.7526x; 2.2744x over previous
#include <cuda_runtime.h>
#include <cuda_bf16.h>
#include <math.h>
#include <stdint.h>

// Problem constants
#define BB 2
#define SS 2048
#define DD 1024
#define HH 16
#define HD 64
#define RA 32
#define RF 512
#define RO 512
#define INTER 4096
#define BS (BB * SS)          // 4096 rows
#define CLAMP_V 1.0e6f
#define LN_EPS 1e-5f

// ---------------------------------------------------------------------------
// Scratch (device globals: allocation-free)
// ---------------------------------------------------------------------------
__device__ float g_normed[BS * DD];
__device__ float g_Tq[BS * (HH * RA)];
__device__ float g_Tk[BS * (HH * RA)];
__device__ float g_Tv[BS * (HH * RA)];
__device__ __nv_bfloat16 g_qh[BB * HH * SS * HD];
__device__ __nv_bfloat16 g_ql[BB * HH * SS * HD];
__device__ __nv_bfloat16 g_kh[BB * HH * SS * HD];
__device__ __nv_bfloat16 g_kl[BB * HH * SS * HD];
__device__ __nv_bfloat16 g_vth[BB * HH * HD * SS];
__device__ __nv_bfloat16 g_vtl[BB * HH * HD * SS];
__device__ float g_attn[BS * DD];
__device__ float g_h[BS * DD];
__device__ float g_tmp[BS * 512];
__device__ float g_ff[BS * INTER];

// ---------------------------------------------------------------------------
// common helpers
// ---------------------------------------------------------------------------
__device__ __forceinline__ void mma16816(float* c, const uint32_t* a, const uint32_t* b) {
    asm volatile(
        "mma.sync.aligned.m16n8k16.row.col.f32.bf16.bf16.f32 "
        "{%0,%1,%2,%3}, {%4,%5,%6,%7}, {%8,%9}, {%0,%1,%2,%3};"
        : "+f"(c[0]), "+f"(c[1]), "+f"(c[2]), "+f"(c[3])
        : "r"(a[0]), "r"(a[1]), "r"(a[2]), "r"(a[3]), "r"(b[0]), "r"(b[1]));
}

__device__ __forceinline__ void packsplit(float f0, float f1, uint32_t& hi, uint32_t& lo) {
    __nv_bfloat162 h = __floats2bfloat162_rn(f0, f1);
    hi = *reinterpret_cast<uint32_t*>(&h);
    __nv_bfloat162 l = __floats2bfloat162_rn(f0 - __bfloat162float(h.x),
                                             f1 - __bfloat162float(h.y));
    lo = *reinterpret_cast<uint32_t*>(&l);
}

#define CP_ASYNC16(dst, src) \
    asm volatile("cp.async.cg.shared.global [%0], [%1], 16;" :: "r"(dst), "l"(src) : "memory")
#define CP_COMMIT() asm volatile("cp.async.commit_group;" ::: "memory")
#define CP_WAIT0() asm volatile("cp.async.wait_group 0;" ::: "memory")
#define CP_WAIT1() asm volatile("cp.async.wait_group 1;" ::: "memory")

__device__ __forceinline__ uint32_t smem_u32(const void* p) {
    uint32_t a;
    asm("{ .reg .u64 t; cvta.to.shared.u64 t, %1; cvt.u32.u64 %0, t; }" : "=r"(a) : "l"(p));
    return a;
}

// ---------------------------------------------------------------------------
// mma.sync bf16 GEMM with 3-term split: C = A[M,K] * W[N,K]^T (+epilogues)
// (unchanged from R3)
// ---------------------------------------------------------------------------
#define MG_STRIDE 80
#define MG_TILE   (128 * MG_STRIDE)
#define MG_STAGE  (4 * MG_TILE)
#define MG_SMEM   (2 * MG_STAGE)

__device__ __forceinline__ void split8(const float4& f0, const float4& f1,
                                       uint4& hi, uint4& lo) {
    float f[8] = {f0.x, f0.y, f0.z, f0.w, f1.x, f1.y, f1.z, f1.w};
    uint32_t h[4], l[4];
#pragma unroll
    for (int j = 0; j < 4; j++) {
        uint32_t u0 = __float_as_uint(f[2 * j]);
        uint32_t u1 = __float_as_uint(f[2 * j + 1]);
        h[j] = __byte_perm(u0, u1, 0x7632);
        float h0 = __uint_as_float(u0 & 0xffff0000u);
        float h1 = __uint_as_float(u1 & 0xffff0000u);
        __nv_bfloat162 lv = __floats2bfloat162_rn(f[2 * j] - h0, f[2 * j + 1] - h1);
        l[j] = *reinterpret_cast<uint32_t*>(&lv);
    }
    hi = make_uint4(h[0], h[1], h[2], h[3]);
    lo = make_uint4(l[0], l[1], l[2], l[3]);
}

template <int EPI>
__global__ __launch_bounds__(256) void mma_gemm(
    int M, int N, int K,
    const float* __restrict__ A, const float* __restrict__ W,
    const float* __restrict__ bias, const float* __restrict__ res,
    float* __restrict__ C)
{
    extern __shared__ char sm[];
    const int tid = threadIdx.x;
    const int lane = tid & 31;
    const int warp = tid >> 5;
    const int wm = (warp >> 2) * 64;
    const int wn = (warp & 3) * 32;
    const int bm = blockIdx.y * 128;
    const int bn = blockIdx.x * 128;

    const int ldRow = tid >> 2;
    const int ldCol = (tid & 3) * 8;

    const int aRow = wm + (lane >> 2);
    const int bRow = wn + (lane >> 2);
    const int fCol = (lane & 3) * 4;

    float acc[4][4][4];
#pragma unroll
    for (int i = 0; i < 4; i++)
#pragma unroll
        for (int j = 0; j < 4; j++)
#pragma unroll
            for (int k = 0; k < 4; k++) acc[i][j][k] = 0.f;

    const float* Ab = A + (size_t)bm * K;
    const float* Wb = W + (size_t)bn * K;
    const int nchunks = K >> 5;

    {
        float4 a0 = *reinterpret_cast<const float4*>(Ab + (size_t)ldRow * K + ldCol);
        float4 a1 = *reinterpret_cast<const float4*>(Ab + (size_t)ldRow * K + ldCol + 4);
        float4 a2 = *reinterpret_cast<const float4*>(Ab + (size_t)(ldRow + 64) * K + ldCol);
        float4 a3 = *reinterpret_cast<const float4*>(Ab + (size_t)(ldRow + 64) * K + ldCol + 4);
        float4 b0 = *reinterpret_cast<const float4*>(Wb + (size_t)ldRow * K + ldCol);
        float4 b1 = *reinterpret_cast<const float4*>(Wb + (size_t)ldRow * K + ldCol + 4);
        float4 b2 = *reinterpret_cast<const float4*>(Wb + (size_t)(ldRow + 64) * K + ldCol);
        float4 b3 = *reinterpret_cast<const float4*>(Wb + (size_t)(ldRow + 64) * K + ldCol + 4);
        uint4 hi, lo;
        const int cb = ldCol * 2;
        split8(a0, a1, hi, lo);
        *reinterpret_cast<uint4*>(sm + 0 * MG_TILE + ldRow * MG_STRIDE + cb) = hi;
        *reinterpret_cast<uint4*>(sm + 1 * MG_TILE + ldRow * MG_STRIDE + cb) = lo;
        split8(a2, a3, hi, lo);
        *reinterpret_cast<uint4*>(sm + 0 * MG_TILE + (ldRow + 64) * MG_STRIDE + cb) = hi;
        *reinterpret_cast<uint4*>(sm + 1 * MG_TILE + (ldRow + 64) * MG_STRIDE + cb) = lo;
        split8(b0, b1, hi, lo);
        *reinterpret_cast<uint4*>(sm + 2 * MG_TILE + ldRow * MG_STRIDE + cb) = hi;
        *reinterpret_cast<uint4*>(sm + 3 * MG_TILE + ldRow * MG_STRIDE + cb) = lo;
        split8(b2, b3, hi, lo);
        *reinterpret_cast<uint4*>(sm + 2 * MG_TILE + (ldRow + 64) * MG_STRIDE + cb) = hi;
        *reinterpret_cast<uint4*>(sm + 3 * MG_TILE + (ldRow + 64) * MG_STRIDE + cb) = lo;
    }
    __syncthreads();

    for (int c = 0; c < nchunks; c++) {
        const int b = c & 1;
        char* st = sm + b * MG_STAGE;

        float4 pa0, pa1, pa2, pa3, pb0, pb1, pb2, pb3;
        const bool havenext = (c + 1 < nchunks);
        if (havenext) {
            const int k0 = (c + 1) << 5;
            pa0 = *reinterpret_cast<const float4*>(Ab + (size_t)ldRow * K + k0 + ldCol);
            pa1 = *reinterpret_cast<const float4*>(Ab + (size_t)ldRow * K + k0 + ldCol + 4);
            pa2 = *reinterpret_cast<const float4*>(Ab + (size_t)(ldRow + 64) * K + k0 + ldCol);
            pa3 = *reinterpret_cast<const float4*>(Ab + (size_t)(ldRow + 64) * K + k0 + ldCol + 4);
            pb0 = *reinterpret_cast<const float4*>(Wb + (size_t)ldRow * K + k0 + ldCol);
            pb1 = *reinterpret_cast<const float4*>(Wb + (size_t)ldRow * K + k0 + ldCol + 4);
            pb2 = *reinterpret_cast<const float4*>(Wb + (size_t)(ldRow + 64) * K + k0 + ldCol);
            pb3 = *reinterpret_cast<const float4*>(Wb + (size_t)(ldRow + 64) * K + k0 + ldCol + 4);
        }

#pragma unroll
        for (int kk = 0; kk < 2; kk++) {
            const int kb = kk * 32;
            uint32_t ah[4][4], bh[4][2];
#pragma unroll
            for (int mt = 0; mt < 4; mt++) {
                const char* p = st + 0 * MG_TILE + (aRow + mt * 16) * MG_STRIDE + fCol + kb;
                ah[mt][0] = *reinterpret_cast<const uint32_t*>(p);
                ah[mt][1] = *reinterpret_cast<const uint32_t*>(p + 8 * MG_STRIDE);
                ah[mt][2] = *reinterpret_cast<const uint32_t*>(p + 16);
                ah[mt][3] = *reinterpret_cast<const uint32_t*>(p + 8 * MG_STRIDE + 16);
            }
#pragma unroll
            for (int nt = 0; nt < 4; nt++) {
                const char* p = st + 2 * MG_TILE + (bRow + nt * 8) * MG_STRIDE + fCol + kb;
                bh[nt][0] = *reinterpret_cast<const uint32_t*>(p);
                bh[nt][1] = *reinterpret_cast<const uint32_t*>(p + 16);
            }
#pragma unroll
            for (int mt = 0; mt < 4; mt++)
#pragma unroll
                for (int nt = 0; nt < 4; nt++)
                    mma16816(acc[mt][nt], ah[mt], bh[nt]);

            {
                uint32_t al[4][4];
#pragma unroll
                for (int mt = 0; mt < 4; mt++) {
                    const char* p = st + 1 * MG_TILE + (aRow + mt * 16) * MG_STRIDE + fCol + kb;
                    al[mt][0] = *reinterpret_cast<const uint32_t*>(p);
                    al[mt][1] = *reinterpret_cast<const uint32_t*>(p + 8 * MG_STRIDE);
                    al[mt][2] = *reinterpret_cast<const uint32_t*>(p + 16);
                    al[mt][3] = *reinterpret_cast<const uint32_t*>(p + 8 * MG_STRIDE + 16);
                }
#pragma unroll
                for (int mt = 0; mt < 4; mt++)
#pragma unroll
                    for (int nt = 0; nt < 4; nt++)
                        mma16816(acc[mt][nt], al[mt], bh[nt]);
            }
            {
                uint32_t bl[4][2];
#pragma unroll
                for (int nt = 0; nt < 4; nt++) {
                    const char* p = st + 3 * MG_TILE + (bRow + nt * 8) * MG_STRIDE + fCol + kb;
                    bl[nt][0] = *reinterpret_cast<const uint32_t*>(p);
                    bl[nt][1] = *reinterpret_cast<const uint32_t*>(p + 16);
                }
#pragma unroll
                for (int mt = 0; mt < 4; mt++)
#pragma unroll
                    for (int nt = 0; nt < 4; nt++)
                        mma16816(acc[mt][nt], ah[mt], bl[nt]);
            }
        }

        if (havenext) {
            char* nst = sm + (b ^ 1) * MG_STAGE;
            const int cb = ldCol * 2;
            uint4 hi, lo;
            split8(pa0, pa1, hi, lo);
            *reinterpret_cast<uint4*>(nst + 0 * MG_TILE + ldRow * MG_STRIDE + cb) = hi;
            *reinterpret_cast<uint4*>(nst + 1 * MG_TILE + ldRow * MG_STRIDE + cb) = lo;
            split8(pa2, pa3, hi, lo);
            *reinterpret_cast<uint4*>(nst + 0 * MG_TILE + (ldRow + 64) * MG_STRIDE + cb) = hi;
            *reinterpret_cast<uint4*>(nst + 1 * MG_TILE + (ldRow + 64) * MG_STRIDE + cb) = lo;
            split8(pb0, pb1, hi, lo);
            *reinterpret_cast<uint4*>(nst + 2 * MG_TILE + ldRow * MG_STRIDE + cb) = hi;
            *reinterpret_cast<uint4*>(nst + 3 * MG_TILE + ldRow * MG_STRIDE + cb) = lo;
            split8(pb2, pb3, hi, lo);
            *reinterpret_cast<uint4*>(nst + 2 * MG_TILE + (ldRow + 64) * MG_STRIDE + cb) = hi;
            *reinterpret_cast<uint4*>(nst + 3 * MG_TILE + (ldRow + 64) * MG_STRIDE + cb) = lo;
        }
        __syncthreads();
    }

#pragma unroll
    for (int mt = 0; mt < 4; mt++) {
#pragma unroll
        for (int nt = 0; nt < 4; nt++) {
            const float* cc = acc[mt][nt];
            const int gr = bm + wm + mt * 16 + (lane >> 2);
            const int gc = bn + wn + nt * 8 + (lane & 3) * 2;
            float b0 = 0.f, b1 = 0.f;
            if (bias) { b0 = bias[gc]; b1 = bias[gc + 1]; }
#pragma unroll
            for (int half = 0; half < 2; half++) {
                const int row = gr + half * 8;
                float v0 = cc[half * 2 + 0] + b0;
                float v1 = cc[half * 2 + 1] + b1;
                if (EPI == 1) {
                    v0 = 0.5f * v0 * (1.0f + erff(v0 * 0.70710678118654752f));
                    v1 = 0.5f * v1 * (1.0f + erff(v1 * 0.70710678118654752f));
                }
                if (EPI == 2) {
                    float2 r2 = *reinterpret_cast<const float2*>(res + (size_t)row * N + gc);
                    v0 += r2.x; v1 += r2.y;
                }
                *reinterpret_cast<float2*>(C + (size_t)row * N + gc) = make_float2(v0, v1);
            }
        }
    }
}

// ---------------------------------------------------------------------------
// LayerNorm
// ---------------------------------------------------------------------------
__global__ __launch_bounds__(256) void ln_kernel(
    const float* __restrict__ x, const float* __restrict__ w,
    const float* __restrict__ b, float* __restrict__ y)
{
    __shared__ float warpred[8];
    __shared__ float s_mean, s_var;
    const int row = blockIdx.x;
    const int tid = threadIdx.x;
    const float* xr = x + (size_t)row * DD;

    float v[4];
    float local = 0.f;
#pragma unroll
    for (int i = 0; i < 4; i++) {
        v[i] = xr[tid + 256 * i];
        local += v[i];
    }
#pragma unroll
    for (int off = 16; off > 0; off >>= 1)
        local += __shfl_xor_sync(0xffffffffu, local, off);
    if ((tid & 31) == 0) warpred[tid >> 5] = local;
    __syncthreads();
    if (tid == 0) {
        float s = 0.f;
#pragma unroll
        for (int i = 0; i < 8; i++) s += warpred[i];
        s_mean = s * (1.0f / DD);
    }
    __syncthreads();
    const float mean = s_mean;

    local = 0.f;
#pragma unroll
    for (int i = 0; i < 4; i++) {
        float d = v[i] - mean;
        local += d * d;
    }
#pragma unroll
    for (int off = 16; off > 0; off >>= 1)
        local += __shfl_xor_sync(0xffffffffu, local, off);
    if ((tid & 31) == 0) warpred[tid >> 5] = local;
    __syncthreads();
    if (tid == 0) {
        float s = 0.f;
#pragma unroll
        for (int i = 0; i < 8; i++) s += warpred[i];
        s_var = s * (1.0f / DD);
    }
    __syncthreads();
    const float rstd = rsqrtf(s_var + LN_EPS);

    float* yr = y + (size_t)row * DD;
#pragma unroll
    for (int i = 0; i < 4; i++) {
        int d = tid + 256 * i;
        yr[d] = (v[i] - mean) * rstd * w[d] + b[d];
    }
}

// ---------------------------------------------------------------------------
// Per-head U projection -> bf16 hi/lo outputs.
// TRANS=0: [B,H,S,HD]; TRANS=1: [B,H,HD,S] (for V).
// ---------------------------------------------------------------------------
template <int TRANS>
__global__ __launch_bounds__(256) void uproj_kernel(
    const float* __restrict__ T, const float* __restrict__ U,
    const float* __restrict__ bias,
    __nv_bfloat16* __restrict__ oh, __nv_bfloat16* __restrict__ ol)
{
    __shared__ float Us[HD][RA + 1];
    __shared__ float Ts[64][RA + 1];
    const int head = blockIdx.y;
    const int s0 = blockIdx.x * 64;
    const int tid = threadIdx.x;

#pragma unroll
    for (int i = 0; i < 8; i++) {
        int idx = tid + 256 * i;
        Us[idx >> 5][idx & 31] = U[(size_t)head * (HD * RA) + idx];
    }
#pragma unroll
    for (int i = 0; i < 8; i++) {
        int idx = tid + 256 * i;
        int sl = idx >> 5, r = idx & 31;
        Ts[sl][r] = T[(size_t)(s0 + sl) * (HH * RA) + head * RA + r];
    }
    __syncthreads();

    const int sl = tid >> 2;
    const int eg = tid & 3;
    float accv[16];
#pragma unroll
    for (int i = 0; i < 16; i++) accv[i] = 0.f;
#pragma unroll
    for (int r = 0; r < RA; r++) {
        float t = Ts[sl][r];
#pragma unroll
        for (int i = 0; i < 16; i++)
            accv[i] += t * Us[eg + 4 * i][r];
    }

    const int bs = s0 + sl;
    const int bb = bs / SS;
    const int s = bs - bb * SS;
#pragma unroll
    for (int i = 0; i < 16; i++) {
        int e = eg + 4 * i;
        float v = accv[i] + bias[head * HD + e];
        v = fminf(fmaxf(v, -CLAMP_V), CLAMP_V);
        __nv_bfloat16 hh = __float2bfloat16(v);
        __nv_bfloat16 ll = __float2bfloat16(v - __bfloat162float(hh));
        size_t idx;
        if (TRANS)
            idx = ((size_t)(bb * HH + head) * HD + e) * SS + s;
        else
            idx = ((size_t)(bb * HH + head) * SS + s) * HD + e;
        oh[idx] = hh;
        ol[idx] = ll;
    }
}

// ---------------------------------------------------------------------------
// Flash attention with mma.sync bf16 (3-term splits).
// Q tiles 128 rows/CTA, key tiles 64. 8 warps x 16 rows.
// smem rows padded to 72 bf16 (144B) -> conflict-free fragment loads.
// ---------------------------------------------------------------------------
#define AT_ROWB 144                   // bytes per padded row
#define AT_Q_BYTES (128 * AT_ROWB)    // 18432 per hi/lo
#define AT_KV_BYTES (64 * AT_ROWB)    // 9216 per array
#define AT_STG_BYTES (4 * AT_KV_BYTES)       // 36864 per stage
#define AT_STG0 (2 * AT_Q_BYTES)             // 36864
#define AT_SMEM (AT_STG0 + 2 * AT_STG_BYTES) // 110592

__device__ __forceinline__ void attn_load_kv(
    uint32_t stg_sb, const __nv_bfloat16* kh, const __nv_bfloat16* kl,
    const __nv_bfloat16* vth, const __nv_bfloat16* vtl,
    int bh, int jt, int tid)
{
#pragma unroll
    for (int i = 0; i < 8; i++) {
        int idx = tid + 256 * i;        // 2048 chunks of 16B
        int a = idx >> 9;               // 512 per array
        int rem = idx & 511;
        int row = rem >> 3;
        int c = rem & 7;
        uint32_t dst = stg_sb + (uint32_t)a * AT_KV_BYTES + row * AT_ROWB + c * 16;
        const __nv_bfloat16* src;
        if (a == 0)      src = kh  + ((size_t)bh * SS + jt * 64 + row) * HD + c * 8;
        else if (a == 1) src = kl  + ((size_t)bh * SS + jt * 64 + row) * HD + c * 8;
        else if (a == 2) src = vth + ((size_t)bh * HD + row) * SS + jt * 64 + c * 8;
        else             src = vtl + ((size_t)bh * HD + row) * SS + jt * 64 + c * 8;
        CP_ASYNC16(dst, src);
    }
}

__global__ __launch_bounds__(256) void attn_mma_kernel(
    const __nv_bfloat16* __restrict__ qh, const __nv_bfloat16* __restrict__ ql,
    const __nv_bfloat16* __restrict__ kh, const __nv_bfloat16* __restrict__ kl,
    const __nv_bfloat16* __restrict__ vth, const __nv_bfloat16* __restrict__ vtl,
    float* __restrict__ O)
{
    extern __shared__ char asmm[];
    const uint32_t sb = smem_u32(asmm);
    const int bh = blockIdx.y;
    const int qt = blockIdx.x;
    const int tid = threadIdx.x;
    const int lane = tid & 31;
    const int warp = tid >> 5;
    const int g = lane >> 2;
    const int t = lane & 3;
    const int wm = warp * 16;

    // Q load via cp.async (hi+lo: 2048 chunks)
#pragma unroll
    for (int i = 0; i < 8; i++) {
        int idx = tid + 256 * i;
        int a = idx >> 10;              // 1024 per array
        int rem = idx & 1023;
        int row = rem >> 3;
        int c = rem & 7;
        uint32_t dst = sb + (uint32_t)a * AT_Q_BYTES + row * AT_ROWB + c * 16;
        const __nv_bfloat16* src = (a ? ql : qh) +
            ((size_t)bh * SS + qt * 128 + row) * HD + c * 8;
        CP_ASYNC16(dst, src);
    }
    attn_load_kv(sb + AT_STG0, kh, kl, vth, vtl, bh, 0, tid);
    CP_COMMIT();

    float m_a = -1e30f, m_b = -1e30f, l_a = 0.f, l_b = 0.f;
    float oacc[8][4];
#pragma unroll
    for (int i = 0; i < 8; i++)
#pragma unroll
        for (int j = 0; j < 4; j++) oacc[i][j] = 0.f;

    const int ntiles = 2 * qt + 2;
    const int rowa = qt * 128 + wm + g;
    const int rowb = rowa + 8;

    for (int jt = 0; jt < ntiles; jt++) {
        if (jt + 1 < ntiles) {
            attn_load_kv(sb + AT_STG0 + ((jt + 1) & 1) * AT_STG_BYTES,
                         kh, kl, vth, vtl, bh, jt + 1, tid);
            CP_COMMIT();
            CP_WAIT1();
        } else {
            CP_WAIT0();
        }
        __syncthreads();

        const char* stg = asmm + AT_STG0 + (jt & 1) * AT_STG_BYTES;
        const char* qhB = asmm;
        const char* qlB = asmm + AT_Q_BYTES;

        // ---- QK^T (3-term split)
        float sacc[8][4];
#pragma unroll
        for (int i = 0; i < 8; i++)
#pragma unroll
            for (int j = 0; j < 4; j++) sacc[i][j] = 0.f;

#pragma unroll
        for (int ks = 0; ks < 4; ks++) {
            const int ab = (wm + g) * AT_ROWB + ks * 32 + t * 4;
            uint32_t ah[4], al[4];
            ah[0] = *reinterpret_cast<const uint32_t*>(qhB + ab);
            ah[1] = *reinterpret_cast<const uint32_t*>(qhB + ab + 8 * AT_ROWB);
            ah[2] = *reinterpret_cast<const uint32_t*>(qhB + ab + 16);
            ah[3] = *reinterpret_cast<const uint32_t*>(qhB + ab + 8 * AT_ROWB + 16);
            al[0] = *reinterpret_cast<const uint32_t*>(qlB + ab);
            al[1] = *reinterpret_cast<const uint32_t*>(qlB + ab + 8 * AT_ROWB);
            al[2] = *reinterpret_cast<const uint32_t*>(qlB + ab + 16);
            al[3] = *reinterpret_cast<const uint32_t*>(qlB + ab + 8 * AT_ROWB + 16);
#pragma unroll
            for (int nt = 0; nt < 8; nt++) {
                const int bb = (nt * 8 + g) * AT_ROWB + ks * 32 + t * 4;
                uint32_t bhf[2], blf[2];
                bhf[0] = *reinterpret_cast<const uint32_t*>(stg + bb);
                bhf[1] = *reinterpret_cast<const uint32_t*>(stg + bb + 16);
                blf[0] = *reinterpret_cast<const uint32_t*>(stg + AT_KV_BYTES + bb);
                blf[1] = *reinterpret_cast<const uint32_t*>(stg + AT_KV_BYTES + bb + 16);
                mma16816(sacc[nt], ah, bhf);
                mma16816(sacc[nt], al, bhf);
                mma16816(sacc[nt], ah, blf);
            }
        }

        // ---- scale + causal mask
        const bool masked = (jt >= 2 * qt);
#pragma unroll
        for (int nt = 0; nt < 8; nt++) {
            const int col = jt * 64 + nt * 8 + 2 * t;
            sacc[nt][0] *= 0.125f; sacc[nt][1] *= 0.125f;
            sacc[nt][2] *= 0.125f; sacc[nt][3] *= 0.125f;
            if (masked) {
                if (col     > rowa) sacc[nt][0] = -1e30f;
                if (col + 1 > rowa) sacc[nt][1] = -1e30f;
                if (col     > rowb) sacc[nt][2] = -1e30f;
                if (col + 1 > rowb) sacc[nt][3] = -1e30f;
            }
        }

        // ---- online softmax
        float mta = -1e30f, mtb = -1e30f;
#pragma unroll
        for (int nt = 0; nt < 8; nt++) {
            mta = fmaxf(mta, fmaxf(sacc[nt][0], sacc[nt][1]));
            mtb = fmaxf(mtb, fmaxf(sacc[nt][2], sacc[nt][3]));
        }
        mta = fmaxf(mta, __shfl_xor_sync(0xffffffffu, mta, 1));
        mta = fmaxf(mta, __shfl_xor_sync(0xffffffffu, mta, 2));
        mtb = fmaxf(mtb, __shfl_xor_sync(0xffffffffu, mtb, 1));
        mtb = fmaxf(mtb, __shfl_xor_sync(0xffffffffu, mtb, 2));

        const float mna = fmaxf(m_a, mta);
        const float mnb = fmaxf(m_b, mtb);
        const float ala = __expf(m_a - mna);
        const float alb = __expf(m_b - mnb);

        float sa = 0.f, sbm = 0.f;
#pragma unroll
        for (int nt = 0; nt < 8; nt++) {
            sacc[nt][0] = __expf(sacc[nt][0] - mna);
            sacc[nt][1] = __expf(sacc[nt][1] - mna);
            sacc[nt][2] = __expf(sacc[nt][2] - mnb);
            sacc[nt][3] = __expf(sacc[nt][3] - mnb);
            sa  += sacc[nt][0] + sacc[nt][1];
            sbm += sacc[nt][2] + sacc[nt][3];
        }
        sa  += __shfl_xor_sync(0xffffffffu, sa, 1);
        sa  += __shfl_xor_sync(0xffffffffu, sa, 2);
        sbm += __shfl_xor_sync(0xffffffffu, sbm, 1);
        sbm += __shfl_xor_sync(0xffffffffu, sbm, 2);

        l_a = l_a * ala + sa;
        l_b = l_b * alb + sbm;
        m_a = mna; m_b = mnb;

#pragma unroll
        for (int nt = 0; nt < 8; nt++) {
            oacc[nt][0] *= ala; oacc[nt][1] *= ala;
            oacc[nt][2] *= alb; oacc[nt][3] *= alb;
        }

        // ---- P·V (3-term split), P frags straight from score accumulators
#pragma unroll
        for (int ks = 0; ks < 4; ks++) {
            uint32_t ph[4], pl[4];
            packsplit(sacc[2 * ks][0],     sacc[2 * ks][1],     ph[0], pl[0]);
            packsplit(sacc[2 * ks][2],     sacc[2 * ks][3],     ph[1], pl[1]);
            packsplit(sacc[2 * ks + 1][0], sacc[2 * ks + 1][1], ph[2], pl[2]);
            packsplit(sacc[2 * ks + 1][2], sacc[2 * ks + 1][3], ph[3], pl[3]);
#pragma unroll
            for (int nt = 0; nt < 8; nt++) {
                const int vb = (nt * 8 + g) * AT_ROWB + ks * 32 + t * 4;
                uint32_t bvh[2], bvl[2];
                bvh[0] = *reinterpret_cast<const uint32_t*>(stg + 2 * AT_KV_BYTES + vb);
                bvh[1] = *reinterpret_cast<const uint32_t*>(stg + 2 * AT_KV_BYTES + vb + 16);
                bvl[0] = *reinterpret_cast<const uint32_t*>(stg + 3 * AT_KV_BYTES + vb);
                bvl[1] = *reinterpret_cast<const uint32_t*>(stg + 3 * AT_KV_BYTES + vb + 16);
                mma16816(oacc[nt], ph, bvh);
                mma16816(oacc[nt], pl, bvh);
                mma16816(oacc[nt], ph, bvl);
            }
        }
        __syncthreads();
    }

    // ---- epilogue
    const int b = bh >> 4;
    const int h = bh & 15;
    const float inva = 1.0f / l_a;
    const float invb = 1.0f / l_b;
#pragma unroll
    for (int nt = 0; nt < 8; nt++) {
        const int d = nt * 8 + 2 * t;
        *reinterpret_cast<float2*>(O + ((size_t)b * SS + rowa) * DD + h * 64 + d) =
            make_float2(oacc[nt][0] * inva, oacc[nt][1] * inva);
        *reinterpret_cast<float2*>(O + ((size_t)b * SS + rowb) * DD + h * 64 + d) =
            make_float2(oacc[nt][2] * invb, oacc[nt][3] * invb);
    }
}

// ---------------------------------------------------------------------------
// Host launch
// ---------------------------------------------------------------------------
extern "C" void kernel_launch(void* const* d_in, const int* in_sizes, int n_in,
                              void* d_out, int out_size)
{
    const float* hidden   = (const float*)d_in[0];
    const float* q_U      = (const float*)d_in[1];
    const float* q_V      = (const float*)d_in[2];
    const float* q_bias   = (const float*)d_in[3];
    const float* k_U      = (const float*)d_in[4];
    const float* k_V      = (const float*)d_in[5];
    const float* k_bias   = (const float*)d_in[6];
    const float* v_U      = (const float*)d_in[7];
    const float* v_V      = (const float*)d_in[8];
    const float* v_bias   = (const float*)d_in[9];
    const float* out_U    = (const float*)d_in[10];
    const float* out_V    = (const float*)d_in[11];
    const float* out_bias = (const float*)d_in[12];
    const float* fc1_U    = (const float*)d_in[13];
    const float* fc1_V    = (const float*)d_in[14];
    const float* fc1_bias = (const float*)d_in[15];
    const float* fc2_U    = (const float*)d_in[16];
    const float* fc2_V    = (const float*)d_in[17];
    const float* fc2_bias = (const float*)d_in[18];
    const float* ln1_w    = (const float*)d_in[19];
    const float* ln1_b    = (const float*)d_in[20];
    const float* ln2_w    = (const float*)d_in[21];
    const float* ln2_b    = (const float*)d_in[22];
    float* out = (float*)d_out;

    float *p_normed, *p_Tq, *p_Tk, *p_Tv, *p_attn, *p_h, *p_tmp, *p_ff;
    __nv_bfloat16 *p_qh, *p_ql, *p_kh, *p_kl, *p_vth, *p_vtl;
    cudaGetSymbolAddress((void**)&p_normed, g_normed);
    cudaGetSymbolAddress((void**)&p_Tq, g_Tq);
    cudaGetSymbolAddress((void**)&p_Tk, g_Tk);
    cudaGetSymbolAddress((void**)&p_Tv, g_Tv);
    cudaGetSymbolAddress((void**)&p_qh, g_qh);
    cudaGetSymbolAddress((void**)&p_ql, g_ql);
    cudaGetSymbolAddress((void**)&p_kh, g_kh);
    cudaGetSymbolAddress((void**)&p_kl, g_kl);
    cudaGetSymbolAddress((void**)&p_vth, g_vth);
    cudaGetSymbolAddress((void**)&p_vtl, g_vtl);
    cudaGetSymbolAddress((void**)&p_attn, g_attn);
    cudaGetSymbolAddress((void**)&p_h, g_h);
    cudaGetSymbolAddress((void**)&p_tmp, g_tmp);
    cudaGetSymbolAddress((void**)&p_ff, g_ff);

    cudaFuncSetAttribute(attn_mma_kernel, cudaFuncAttributeMaxDynamicSharedMemorySize, AT_SMEM);
    cudaFuncSetAttribute(mma_gemm<0>, cudaFuncAttributeMaxDynamicSharedMemorySize, MG_SMEM);
    cudaFuncSetAttribute(mma_gemm<1>, cudaFuncAttributeMaxDynamicSharedMemorySize, MG_SMEM);
    cudaFuncSetAttribute(mma_gemm<2>, cudaFuncAttributeMaxDynamicSharedMemorySize, MG_SMEM);

    // 1. LN1
    ln_kernel<<<BS, 256>>>(hidden, ln1_w, ln1_b, p_normed);

    // 2. rank projections
    {
        dim3 g(512 / 128, BS / 128);
        mma_gemm<0><<<g, 256, MG_SMEM>>>(BS, 512, DD, p_normed, q_V, nullptr, nullptr, p_Tq);
        mma_gemm<0><<<g, 256, MG_SMEM>>>(BS, 512, DD, p_normed, k_V, nullptr, nullptr, p_Tk);
        mma_gemm<0><<<g, 256, MG_SMEM>>>(BS, 512, DD, p_normed, v_V, nullptr, nullptr, p_Tv);
    }

    // 3. U projection + bias + clip -> bf16 hi/lo q,k (row) and v (transposed)
    {
        dim3 g(BS / 64, HH);
        uproj_kernel<0><<<g, 256>>>(p_Tq, q_U, q_bias, p_qh, p_ql);
        uproj_kernel<0><<<g, 256>>>(p_Tk, k_U, k_bias, p_kh, p_kl);
        uproj_kernel<1><<<g, 256>>>(p_Tv, v_U, v_bias, p_vth, p_vtl);
    }

    // 4. causal attention (tensor cores) -> attn [B,S,D]
    {
        dim3 g(SS / 128, BB * HH);
        attn_mma_kernel<<<g, 256, AT_SMEM>>>(p_qh, p_ql, p_kh, p_kl, p_vth, p_vtl, p_attn);
    }

    // 5-6. out projection (low rank) + residual
    {
        dim3 g1(RO / 128, BS / 128);
        mma_gemm<0><<<g1, 256, MG_SMEM>>>(BS, RO, DD, p_attn, out_V, nullptr, nullptr, p_tmp);
        dim3 g2(DD / 128, BS / 128);
        mma_gemm<2><<<g2, 256, MG_SMEM>>>(BS, DD, RO, p_tmp, out_U, out_bias, hidden, p_h);
    }

    // 7. LN2
    ln_kernel<<<BS, 256>>>(p_h, ln2_w, ln2_b, p_normed);

    // 8-9. FC1 (low rank) + bias + exact GELU
    {
        dim3 g1(RF / 128, BS / 128);
        mma_gemm<0><<<g1, 256, MG_SMEM>>>(BS, RF, DD, p_normed, fc1_V, nullptr, nullptr, p_tmp);
        dim3 g2(INTER / 128, BS / 128);
        mma_gemm<1><<<g2, 256, MG_SMEM>>>(BS, INTER, RF, p_tmp, fc1_U, fc1_bias, nullptr, p_ff);
    }

    // 10-11. FC2 (low rank) + bias + residual -> out
    {
        dim3 g1(RF / 128, BS / 128);
        mma_gemm<0><<<g1, 256, MG_SMEM>>>(BS, RF, INTER, p_ff, fc2_V, nullptr, nullptr, p_tmp);
        dim3 g2(DD / 128, BS / 128);
        mma_gemm<2><<<g2, 256, MG_SMEM>>>(BS, DD, RF, p_tmp, fc2_U, fc2_bias, p_h, out);
    }
    (void)in_sizes; (void)n_in; (void)out_size;
}